// round 1
// baseline (speedup 1.0000x reference)
#include <cuda_runtime.h>
#include <cuda_bf16.h>
#include <cstddef>

#define S_LEN 4096
#define DMODEL 768
#define NHEAD 12
#define HDIM 64

// scratch: Q/K/V [3][H][S][HD] and concat [S][D]
__device__ float g_qkv[3 * NHEAD * S_LEN * HDIM];
__device__ float g_concat[(size_t)S_LEN * DMODEL];

// ---------------------------------------------------------------------------
// Kernel 1: fused per-head QKV projection.
// grid (S/128, 3*H), block 256. Tile 128(S) x 64(HD), K-loop over 768.
// ---------------------------------------------------------------------------
__global__ void __launch_bounds__(256) qkv_kernel(
    const float* __restrict__ x,
    const float* __restrict__ Wq, const float* __restrict__ Wk, const float* __restrict__ Wv,
    const float* __restrict__ bq, const float* __restrict__ bk, const float* __restrict__ bv)
{
    const int mat = blockIdx.y / NHEAD;      // 0=q 1=k 2=v
    const int h   = blockIdx.y % NHEAD;
    const int s0  = blockIdx.x * 128;

    const float* W    = (mat == 0 ? Wq : (mat == 1 ? Wk : Wv)) + (size_t)h * DMODEL * HDIM;
    const float* bias = (mat == 0 ? bq : (mat == 1 ? bk : bv)) + h * HDIM;
    float* O = g_qkv + ((size_t)(mat * NHEAD + h)) * S_LEN * HDIM;

    __shared__ float sA[16][132];   // k-major transposed A: sA[k][row]
    __shared__ float sB[16][64];    // sB[k][e]

    const int tid = threadIdx.x;
    const int tx = tid & 15, ty = tid >> 4;
    const int la_row = tid >> 2;
    const int la_cg  = (tid & 3) * 4;
    const int lb_k   = tid >> 4;
    const int lb_e   = (tid & 15) * 4;

    float acc[8][4];
#pragma unroll
    for (int i = 0; i < 8; i++)
#pragma unroll
        for (int j = 0; j < 4; j++) acc[i][j] = 0.f;

    for (int k0 = 0; k0 < DMODEL; k0 += 16) {
#pragma unroll
        for (int rr = 0; rr < 2; rr++) {
            int row = la_row + rr * 64;
            float4 v = *(const float4*)&x[(size_t)(s0 + row) * DMODEL + k0 + la_cg];
            sA[la_cg + 0][row] = v.x;
            sA[la_cg + 1][row] = v.y;
            sA[la_cg + 2][row] = v.z;
            sA[la_cg + 3][row] = v.w;
        }
        *(float4*)&sB[lb_k][lb_e] = *(const float4*)&W[(size_t)(k0 + lb_k) * HDIM + lb_e];
        __syncthreads();
#pragma unroll
        for (int k = 0; k < 16; k++) {
            float a[8], b[4];
            *(float4*)a       = *(const float4*)&sA[k][ty * 8];
            *(float4*)(a + 4) = *(const float4*)&sA[k][ty * 8 + 4];
            *(float4*)b       = *(const float4*)&sB[k][tx * 4];
#pragma unroll
            for (int i = 0; i < 8; i++)
#pragma unroll
                for (int j = 0; j < 4; j++)
                    acc[i][j] = fmaf(a[i], b[j], acc[i][j]);
        }
        __syncthreads();
    }

    float bb[4];
    *(float4*)bb = *(const float4*)&bias[tx * 4];
#pragma unroll
    for (int i = 0; i < 8; i++) {
        int s = s0 + ty * 8 + i;
        float4 r = make_float4(acc[i][0] + bb[0], acc[i][1] + bb[1],
                               acc[i][2] + bb[2], acc[i][3] + bb[3]);
        *(float4*)&O[(size_t)s * HDIM + tx * 4] = r;
    }
}

// ---------------------------------------------------------------------------
// Kernel 2: flash attention per head, fp32 online softmax.
// grid (S/128, H), block 256, dynamic smem 102400 B.
// Q tile 128 rows, K tile 64. Writes result directly into concat layout.
// ---------------------------------------------------------------------------
#define ATTN_SMEM_BYTES (size_t)((132 * 64 * 2 + 68 * 64 * 2) * 4)

__global__ void __launch_bounds__(256) attn_kernel()
{
    extern __shared__ float sm[];
    float* sQt = sm;                     // [64][132]  e-major, prescaled
    float* sPt = sQt + 64 * 132;         // [64][132]  k-major P
    float* sKt = sPt + 64 * 132;         // [64][68]   e-major K
    float* sV  = sKt + 64 * 68;          // [64][68]   natural V

    const int h  = blockIdx.y;
    const int q0 = blockIdx.x * 128;
    const float* Q = g_qkv + ((size_t)(0 * NHEAD + h)) * S_LEN * HDIM;
    const float* K = g_qkv + ((size_t)(1 * NHEAD + h)) * S_LEN * HDIM;
    const float* V = g_qkv + ((size_t)(2 * NHEAD + h)) * S_LEN * HDIM;

    const int tid = threadIdx.x;
    const int tx = tid & 15, ty = tid >> 4;

    // load Q transposed + prescaled by 1/sqrt(64) = 0.125
    {
        int r = tid >> 2;
        int eb = (tid & 3) * 4;
#pragma unroll
        for (int pass = 0; pass < 2; pass++) {
            int rr = r + pass * 64;
#pragma unroll
            for (int ep = 0; ep < 4; ep++) {
                int e = eb + ep * 16;
                float4 v = *(const float4*)&Q[(size_t)(q0 + rr) * HDIM + e];
                sQt[(e + 0) * 132 + rr] = v.x * 0.125f;
                sQt[(e + 1) * 132 + rr] = v.y * 0.125f;
                sQt[(e + 2) * 132 + rr] = v.z * 0.125f;
                sQt[(e + 3) * 132 + rr] = v.w * 0.125f;
            }
        }
    }

    float m_i[8], l_i[8], acc[8][4];
#pragma unroll
    for (int i = 0; i < 8; i++) {
        m_i[i] = -1e30f; l_i[i] = 0.f;
#pragma unroll
        for (int j = 0; j < 4; j++) acc[i][j] = 0.f;
    }

    for (int kt = 0; kt < S_LEN / 64; kt++) {
        const int s0 = kt * 64;
        __syncthreads();   // prior iteration's sKt/sV/sPt reads done
        // load K transposed
        {
            int c = tid >> 2;
            int eb = (tid & 3) * 4;
#pragma unroll
            for (int ep = 0; ep < 4; ep++) {
                int e = eb + ep * 16;
                float4 v = *(const float4*)&K[(size_t)(s0 + c) * HDIM + e];
                sKt[(e + 0) * 68 + c] = v.x;
                sKt[(e + 1) * 68 + c] = v.y;
                sKt[(e + 2) * 68 + c] = v.z;
                sKt[(e + 3) * 68 + c] = v.w;
            }
        }
        // load V natural
        {
            int e = (tid & 15) * 4;
            int rb = tid >> 4;
#pragma unroll
            for (int p = 0; p < 4; p++) {
                int rr = rb + p * 16;
                *(float4*)&sV[rr * 68 + e] = *(const float4*)&V[(size_t)(s0 + rr) * HDIM + e];
            }
        }
        __syncthreads();

        // S = Q K^T  (thread: rows ty*8..+8, cols tx*4..+4)
        float sv[8][4];
#pragma unroll
        for (int i = 0; i < 8; i++)
#pragma unroll
            for (int j = 0; j < 4; j++) sv[i][j] = 0.f;
#pragma unroll 8
        for (int e = 0; e < 64; e++) {
            float a[8], b[4];
            *(float4*)a       = *(const float4*)&sQt[e * 132 + ty * 8];
            *(float4*)(a + 4) = *(const float4*)&sQt[e * 132 + ty * 8 + 4];
            *(float4*)b       = *(const float4*)&sKt[e * 68 + tx * 4];
#pragma unroll
            for (int i = 0; i < 8; i++)
#pragma unroll
                for (int j = 0; j < 4; j++)
                    sv[i][j] = fmaf(a[i], b[j], sv[i][j]);
        }

        // online softmax (row reductions across the 16 tx lanes)
#pragma unroll
        for (int i = 0; i < 8; i++) {
            float tm = fmaxf(fmaxf(sv[i][0], sv[i][1]), fmaxf(sv[i][2], sv[i][3]));
            tm = fmaxf(tm, __shfl_xor_sync(0xffffffffu, tm, 1));
            tm = fmaxf(tm, __shfl_xor_sync(0xffffffffu, tm, 2));
            tm = fmaxf(tm, __shfl_xor_sync(0xffffffffu, tm, 4));
            tm = fmaxf(tm, __shfl_xor_sync(0xffffffffu, tm, 8));
            float mnew  = fmaxf(m_i[i], tm);
            float alpha = __expf(m_i[i] - mnew);
            m_i[i] = mnew;
            float rs = 0.f;
#pragma unroll
            for (int j = 0; j < 4; j++) {
                float p = __expf(sv[i][j] - mnew);
                sv[i][j] = p;
                rs += p;
            }
            rs += __shfl_xor_sync(0xffffffffu, rs, 1);
            rs += __shfl_xor_sync(0xffffffffu, rs, 2);
            rs += __shfl_xor_sync(0xffffffffu, rs, 4);
            rs += __shfl_xor_sync(0xffffffffu, rs, 8);
            l_i[i] = l_i[i] * alpha + rs;
#pragma unroll
            for (int j = 0; j < 4; j++) acc[i][j] *= alpha;
        }

        // store P transposed: sPt[c][r]
#pragma unroll
        for (int j = 0; j < 4; j++) {
            int c = tx * 4 + j;
            float4 v0 = make_float4(sv[0][j], sv[1][j], sv[2][j], sv[3][j]);
            float4 v1 = make_float4(sv[4][j], sv[5][j], sv[6][j], sv[7][j]);
            *(float4*)&sPt[c * 132 + ty * 8]     = v0;
            *(float4*)&sPt[c * 132 + ty * 8 + 4] = v1;
        }
        __syncthreads();

        // O += P @ V
#pragma unroll 8
        for (int k = 0; k < 64; k++) {
            float a[8], b[4];
            *(float4*)a       = *(const float4*)&sPt[k * 132 + ty * 8];
            *(float4*)(a + 4) = *(const float4*)&sPt[k * 132 + ty * 8 + 4];
            *(float4*)b       = *(const float4*)&sV[k * 68 + tx * 4];
#pragma unroll
            for (int i = 0; i < 8; i++)
#pragma unroll
                for (int j = 0; j < 4; j++)
                    acc[i][j] = fmaf(a[i], b[j], acc[i][j]);
        }
    }

    // epilogue: normalize and write into concat layout [s][h*64+e]
#pragma unroll
    for (int i = 0; i < 8; i++) {
        int s = q0 + ty * 8 + i;
        float inv = 1.f / l_i[i];
        float4 r = make_float4(acc[i][0] * inv, acc[i][1] * inv,
                               acc[i][2] * inv, acc[i][3] * inv);
        *(float4*)&g_concat[(size_t)s * DMODEL + h * HDIM + tx * 4] = r;
    }
}

// ---------------------------------------------------------------------------
// Kernel 3: output projection  out = concat @ Wo + bo
// grid (S/128, D/64), block 256.
// ---------------------------------------------------------------------------
__global__ void __launch_bounds__(256) proj_kernel(
    const float* __restrict__ Wo, const float* __restrict__ bo, float* __restrict__ out)
{
    const int s0 = blockIdx.x * 128;
    const int n0 = blockIdx.y * 64;

    __shared__ float sA[16][132];
    __shared__ float sB[16][64];

    const int tid = threadIdx.x;
    const int tx = tid & 15, ty = tid >> 4;
    const int la_row = tid >> 2;
    const int la_cg  = (tid & 3) * 4;
    const int lb_k   = tid >> 4;
    const int lb_e   = (tid & 15) * 4;

    float acc[8][4];
#pragma unroll
    for (int i = 0; i < 8; i++)
#pragma unroll
        for (int j = 0; j < 4; j++) acc[i][j] = 0.f;

    for (int k0 = 0; k0 < DMODEL; k0 += 16) {
#pragma unroll
        for (int rr = 0; rr < 2; rr++) {
            int row = la_row + rr * 64;
            float4 v = *(const float4*)&g_concat[(size_t)(s0 + row) * DMODEL + k0 + la_cg];
            sA[la_cg + 0][row] = v.x;
            sA[la_cg + 1][row] = v.y;
            sA[la_cg + 2][row] = v.z;
            sA[la_cg + 3][row] = v.w;
        }
        *(float4*)&sB[lb_k][lb_e] = *(const float4*)&Wo[(size_t)(k0 + lb_k) * DMODEL + n0 + lb_e];
        __syncthreads();
#pragma unroll
        for (int k = 0; k < 16; k++) {
            float a[8], b[4];
            *(float4*)a       = *(const float4*)&sA[k][ty * 8];
            *(float4*)(a + 4) = *(const float4*)&sA[k][ty * 8 + 4];
            *(float4*)b       = *(const float4*)&sB[k][tx * 4];
#pragma unroll
            for (int i = 0; i < 8; i++)
#pragma unroll
                for (int j = 0; j < 4; j++)
                    acc[i][j] = fmaf(a[i], b[j], acc[i][j]);
        }
        __syncthreads();
    }

    float bb[4];
    *(float4*)bb = *(const float4*)&bo[n0 + tx * 4];
#pragma unroll
    for (int i = 0; i < 8; i++) {
        int s = s0 + ty * 8 + i;
        float4 r = make_float4(acc[i][0] + bb[0], acc[i][1] + bb[1],
                               acc[i][2] + bb[2], acc[i][3] + bb[3]);
        *(float4*)&out[(size_t)s * DMODEL + n0 + tx * 4] = r;
    }
}

// ---------------------------------------------------------------------------
extern "C" void kernel_launch(void* const* d_in, const int* in_sizes, int n_in,
                              void* d_out, int out_size)
{
    const float* x  = (const float*)d_in[0];
    const float* Wq = (const float*)d_in[1];
    const float* Wk = (const float*)d_in[2];
    const float* Wv = (const float*)d_in[3];
    const float* bq = (const float*)d_in[4];
    const float* bk = (const float*)d_in[5];
    const float* bv = (const float*)d_in[6];
    const float* Wo = (const float*)d_in[7];
    const float* bo = (const float*)d_in[8];
    float* out = (float*)d_out;

    cudaFuncSetAttribute(attn_kernel, cudaFuncAttributeMaxDynamicSharedMemorySize,
                         (int)ATTN_SMEM_BYTES);

    qkv_kernel<<<dim3(S_LEN / 128, 3 * NHEAD), 256>>>(x, Wq, Wk, Wv, bq, bk, bv);
    attn_kernel<<<dim3(S_LEN / 128, NHEAD), 256, ATTN_SMEM_BYTES>>>();
    proj_kernel<<<dim3(S_LEN / 128, DMODEL / 64), 256>>>(Wo, bo, out);
}

// round 2
// speedup vs baseline: 1.8108x; 1.8108x over previous
#include <cuda_runtime.h>
#include <cuda_bf16.h>
#include <cstddef>
#include <cstdint>

#define S_LEN 4096
#define DMODEL 768
#define NHEAD 12
#define HDIM 64
#define QTILE 128
#define KTILE 64

// scratch: Q/K/V [3][H][S][HD] and concat [S][D]
__device__ float g_qkv[3 * NHEAD * S_LEN * HDIM];
__device__ float g_concat[(size_t)S_LEN * DMODEL];

__device__ __forceinline__ uint32_t f2tf(float f) {
    uint32_t r;
    asm("cvt.rna.tf32.f32 %0, %1;" : "=r"(r) : "f"(f));
    return r;
}

__device__ __forceinline__ void mma_tf32(float c[4],
                                         uint32_t a0, uint32_t a1, uint32_t a2, uint32_t a3,
                                         uint32_t b0, uint32_t b1) {
    asm volatile(
        "mma.sync.aligned.m16n8k8.row.col.f32.tf32.tf32.f32 "
        "{%0,%1,%2,%3}, {%4,%5,%6,%7}, {%8,%9}, {%0,%1,%2,%3};"
        : "+f"(c[0]), "+f"(c[1]), "+f"(c[2]), "+f"(c[3])
        : "r"(a0), "r"(a1), "r"(a2), "r"(a3), "r"(b0), "r"(b1));
}

// ---------------------------------------------------------------------------
// Kernel 1: fused per-head QKV projection (fp32, unchanged from R1).
// ---------------------------------------------------------------------------
__global__ void __launch_bounds__(256) qkv_kernel(
    const float* __restrict__ x,
    const float* __restrict__ Wq, const float* __restrict__ Wk, const float* __restrict__ Wv,
    const float* __restrict__ bq, const float* __restrict__ bk, const float* __restrict__ bv)
{
    const int mat = blockIdx.y / NHEAD;
    const int h   = blockIdx.y % NHEAD;
    const int s0  = blockIdx.x * 128;

    const float* W    = (mat == 0 ? Wq : (mat == 1 ? Wk : Wv)) + (size_t)h * DMODEL * HDIM;
    const float* bias = (mat == 0 ? bq : (mat == 1 ? bk : bv)) + h * HDIM;
    float* O = g_qkv + ((size_t)(mat * NHEAD + h)) * S_LEN * HDIM;

    __shared__ float sA[16][132];
    __shared__ float sB[16][64];

    const int tid = threadIdx.x;
    const int tx = tid & 15, ty = tid >> 4;
    const int la_row = tid >> 2;
    const int la_cg  = (tid & 3) * 4;
    const int lb_k   = tid >> 4;
    const int lb_e   = (tid & 15) * 4;

    float acc[8][4];
#pragma unroll
    for (int i = 0; i < 8; i++)
#pragma unroll
        for (int j = 0; j < 4; j++) acc[i][j] = 0.f;

    for (int k0 = 0; k0 < DMODEL; k0 += 16) {
#pragma unroll
        for (int rr = 0; rr < 2; rr++) {
            int row = la_row + rr * 64;
            float4 v = *(const float4*)&x[(size_t)(s0 + row) * DMODEL + k0 + la_cg];
            sA[la_cg + 0][row] = v.x;
            sA[la_cg + 1][row] = v.y;
            sA[la_cg + 2][row] = v.z;
            sA[la_cg + 3][row] = v.w;
        }
        *(float4*)&sB[lb_k][lb_e] = *(const float4*)&W[(size_t)(k0 + lb_k) * HDIM + lb_e];
        __syncthreads();
#pragma unroll
        for (int k = 0; k < 16; k++) {
            float a[8], b[4];
            *(float4*)a       = *(const float4*)&sA[k][ty * 8];
            *(float4*)(a + 4) = *(const float4*)&sA[k][ty * 8 + 4];
            *(float4*)b       = *(const float4*)&sB[k][tx * 4];
#pragma unroll
            for (int i = 0; i < 8; i++)
#pragma unroll
                for (int j = 0; j < 4; j++)
                    acc[i][j] = fmaf(a[i], b[j], acc[i][j]);
        }
        __syncthreads();
    }

    float bb[4];
    *(float4*)bb = *(const float4*)&bias[tx * 4];
#pragma unroll
    for (int i = 0; i < 8; i++) {
        int s = s0 + ty * 8 + i;
        float4 r = make_float4(acc[i][0] + bb[0], acc[i][1] + bb[1],
                               acc[i][2] + bb[2], acc[i][3] + bb[3]);
        *(float4*)&O[(size_t)s * HDIM + tx * 4] = r;
    }
}

// ---------------------------------------------------------------------------
// Kernel 2: flash attention with tf32 mma.sync tensor cores.
// grid (32, 12), block 256 (8 warps x 16 query rows). K-tile = 64.
// Q fragments live in registers for the whole kernel (prescaled by 0.125).
// ---------------------------------------------------------------------------
#define SK_STRIDE 68   // bank = 4*quad + qt  -> conflict-free for K B-frags
#define SV_STRIDE 72   // bank = 8*qt + quad  -> conflict-free for V B-frags
#define SP_STRIDE 68
#define ATTN_SMEM_WORDS (KTILE * SK_STRIDE + KTILE * SV_STRIDE + QTILE * SP_STRIDE)
#define ATTN_SMEM_BYTES ((size_t)ATTN_SMEM_WORDS * 4)

__global__ void __launch_bounds__(256) attn_kernel()
{
    extern __shared__ uint32_t sm[];
    uint32_t* sK = sm;                           // [64][68] tf32, K[key][e]
    uint32_t* sV = sK + KTILE * SK_STRIDE;       // [64][72] tf32, V[key][e]
    uint32_t* sP = sV + KTILE * SV_STRIDE;       // [128][68] tf32, warp-private P

    const int h  = blockIdx.y;
    const int q0 = blockIdx.x * QTILE;
    const float* Q = g_qkv + ((size_t)(0 * NHEAD + h)) * S_LEN * HDIM;
    const float* K = g_qkv + ((size_t)(1 * NHEAD + h)) * S_LEN * HDIM;
    const float* V = g_qkv + ((size_t)(2 * NHEAD + h)) * S_LEN * HDIM;

    const int tid  = threadIdx.x;
    const int wid  = tid >> 5;
    const int lane = tid & 31;
    const int quad = lane >> 2;   // 0..7
    const int qt   = lane & 3;    // 0..3
    const int mrow = q0 + wid * 16;

    // Q A-fragments, prescaled by 1/sqrt(64), held in registers
    uint32_t qa[8][4];
#pragma unroll
    for (int ks = 0; ks < 8; ks++) {
        int c = ks * 8 + qt;
        qa[ks][0] = f2tf(Q[(size_t)(mrow + quad    ) * HDIM + c    ] * 0.125f);
        qa[ks][1] = f2tf(Q[(size_t)(mrow + quad + 8) * HDIM + c    ] * 0.125f);
        qa[ks][2] = f2tf(Q[(size_t)(mrow + quad    ) * HDIM + c + 4] * 0.125f);
        qa[ks][3] = f2tf(Q[(size_t)(mrow + quad + 8) * HDIM + c + 4] * 0.125f);
    }

    float o[8][4];
#pragma unroll
    for (int n = 0; n < 8; n++)
#pragma unroll
        for (int j = 0; j < 4; j++) o[n][j] = 0.f;
    float m0 = -1e30f, m1 = -1e30f, l0 = 0.f, l1 = 0.f;

    uint32_t* pbase = sP + (wid * 16) * SP_STRIDE;

    for (int kt = 0; kt < S_LEN / KTILE; kt++) {
        const int s0 = kt * KTILE;
        __syncthreads();  // sK/sV (and sP) consumers of previous tile done

        // stage K and V tiles (fp32 -> tf32)
#pragma unroll
        for (int i = tid; i < KTILE * 16; i += 256) {
            int r = i >> 4, cg = (i & 15) * 4;
            float4 kv = *(const float4*)&K[(size_t)(s0 + r) * HDIM + cg];
            uint32_t* dk = &sK[r * SK_STRIDE + cg];
            dk[0] = f2tf(kv.x); dk[1] = f2tf(kv.y); dk[2] = f2tf(kv.z); dk[3] = f2tf(kv.w);
            float4 vv = *(const float4*)&V[(size_t)(s0 + r) * HDIM + cg];
            uint32_t* dv = &sV[r * SV_STRIDE + cg];
            dv[0] = f2tf(vv.x); dv[1] = f2tf(vv.y); dv[2] = f2tf(vv.z); dv[3] = f2tf(vv.w);
        }
        __syncthreads();

        // ---- S = Q K^T (16 x 64 per warp) ----
        float sc[8][4];
#pragma unroll
        for (int n = 0; n < 8; n++)
#pragma unroll
            for (int j = 0; j < 4; j++) sc[n][j] = 0.f;

#pragma unroll
        for (int ks = 0; ks < 8; ks++) {
#pragma unroll
            for (int n = 0; n < 8; n++) {
                const uint32_t* kb = &sK[(n * 8 + quad) * SK_STRIDE + ks * 8 + qt];
                mma_tf32(sc[n], qa[ks][0], qa[ks][1], qa[ks][2], qa[ks][3], kb[0], kb[4]);
            }
        }

        // ---- online softmax (rows quad and quad+8 of this warp) ----
        float rmax0 = -1e30f, rmax1 = -1e30f;
#pragma unroll
        for (int n = 0; n < 8; n++) {
            rmax0 = fmaxf(rmax0, fmaxf(sc[n][0], sc[n][1]));
            rmax1 = fmaxf(rmax1, fmaxf(sc[n][2], sc[n][3]));
        }
        rmax0 = fmaxf(rmax0, __shfl_xor_sync(0xffffffffu, rmax0, 1));
        rmax0 = fmaxf(rmax0, __shfl_xor_sync(0xffffffffu, rmax0, 2));
        rmax1 = fmaxf(rmax1, __shfl_xor_sync(0xffffffffu, rmax1, 1));
        rmax1 = fmaxf(rmax1, __shfl_xor_sync(0xffffffffu, rmax1, 2));

        float nm0 = fmaxf(m0, rmax0), nm1 = fmaxf(m1, rmax1);
        float al0 = __expf(m0 - nm0), al1 = __expf(m1 - nm1);
        m0 = nm0; m1 = nm1;

        float rs0 = 0.f, rs1 = 0.f;
#pragma unroll
        for (int n = 0; n < 8; n++) {
            sc[n][0] = __expf(sc[n][0] - nm0); rs0 += sc[n][0];
            sc[n][1] = __expf(sc[n][1] - nm0); rs0 += sc[n][1];
            sc[n][2] = __expf(sc[n][2] - nm1); rs1 += sc[n][2];
            sc[n][3] = __expf(sc[n][3] - nm1); rs1 += sc[n][3];
        }
        rs0 += __shfl_xor_sync(0xffffffffu, rs0, 1);
        rs0 += __shfl_xor_sync(0xffffffffu, rs0, 2);
        rs1 += __shfl_xor_sync(0xffffffffu, rs1, 1);
        rs1 += __shfl_xor_sync(0xffffffffu, rs1, 2);
        l0 = l0 * al0 + rs0;
        l1 = l1 * al1 + rs1;

#pragma unroll
        for (int n = 0; n < 8; n++) {
            o[n][0] *= al0; o[n][1] *= al0;
            o[n][2] *= al1; o[n][3] *= al1;
        }

        // ---- stage P (tf32) into warp-private smem for A-fragment reload ----
#pragma unroll
        for (int n = 0; n < 8; n++) {
            int c = n * 8 + 2 * qt;
            pbase[(quad    ) * SP_STRIDE + c    ] = f2tf(sc[n][0]);
            pbase[(quad    ) * SP_STRIDE + c + 1] = f2tf(sc[n][1]);
            pbase[(quad + 8) * SP_STRIDE + c    ] = f2tf(sc[n][2]);
            pbase[(quad + 8) * SP_STRIDE + c + 1] = f2tf(sc[n][3]);
        }
        __syncwarp();

        // ---- O += P V ----
#pragma unroll
        for (int ks = 0; ks < 8; ks++) {
            uint32_t pa0 = pbase[(quad    ) * SP_STRIDE + ks * 8 + qt];
            uint32_t pa1 = pbase[(quad + 8) * SP_STRIDE + ks * 8 + qt];
            uint32_t pa2 = pbase[(quad    ) * SP_STRIDE + ks * 8 + qt + 4];
            uint32_t pa3 = pbase[(quad + 8) * SP_STRIDE + ks * 8 + qt + 4];
#pragma unroll
            for (int n = 0; n < 8; n++) {
                const uint32_t* vb = &sV[(ks * 8 + qt) * SV_STRIDE + n * 8 + quad];
                mma_tf32(o[n], pa0, pa1, pa2, pa3, vb[0], vb[4 * SV_STRIDE]);
            }
        }
    }

    // ---- epilogue: normalize, write into concat layout ----
    float il0 = 1.f / l0, il1 = 1.f / l1;
    const int r0g = mrow + quad, r1g = mrow + quad + 8;
#pragma unroll
    for (int n = 0; n < 8; n++) {
        int col = h * HDIM + n * 8 + 2 * qt;
        float2 w0 = make_float2(o[n][0] * il0, o[n][1] * il0);
        float2 w1 = make_float2(o[n][2] * il1, o[n][3] * il1);
        *(float2*)&g_concat[(size_t)r0g * DMODEL + col] = w0;
        *(float2*)&g_concat[(size_t)r1g * DMODEL + col] = w1;
    }
}

// ---------------------------------------------------------------------------
// Kernel 3: output projection (fp32, unchanged from R1).
// ---------------------------------------------------------------------------
__global__ void __launch_bounds__(256) proj_kernel(
    const float* __restrict__ Wo, const float* __restrict__ bo, float* __restrict__ out)
{
    const int s0 = blockIdx.x * 128;
    const int n0 = blockIdx.y * 64;

    __shared__ float sA[16][132];
    __shared__ float sB[16][64];

    const int tid = threadIdx.x;
    const int tx = tid & 15, ty = tid >> 4;
    const int la_row = tid >> 2;
    const int la_cg  = (tid & 3) * 4;
    const int lb_k   = tid >> 4;
    const int lb_e   = (tid & 15) * 4;

    float acc[8][4];
#pragma unroll
    for (int i = 0; i < 8; i++)
#pragma unroll
        for (int j = 0; j < 4; j++) acc[i][j] = 0.f;

    for (int k0 = 0; k0 < DMODEL; k0 += 16) {
#pragma unroll
        for (int rr = 0; rr < 2; rr++) {
            int row = la_row + rr * 64;
            float4 v = *(const float4*)&g_concat[(size_t)(s0 + row) * DMODEL + k0 + la_cg];
            sA[la_cg + 0][row] = v.x;
            sA[la_cg + 1][row] = v.y;
            sA[la_cg + 2][row] = v.z;
            sA[la_cg + 3][row] = v.w;
        }
        *(float4*)&sB[lb_k][lb_e] = *(const float4*)&Wo[(size_t)(k0 + lb_k) * DMODEL + n0 + lb_e];
        __syncthreads();
#pragma unroll
        for (int k = 0; k < 16; k++) {
            float a[8], b[4];
            *(float4*)a       = *(const float4*)&sA[k][ty * 8];
            *(float4*)(a + 4) = *(const float4*)&sA[k][ty * 8 + 4];
            *(float4*)b       = *(const float4*)&sB[k][tx * 4];
#pragma unroll
            for (int i = 0; i < 8; i++)
#pragma unroll
                for (int j = 0; j < 4; j++)
                    acc[i][j] = fmaf(a[i], b[j], acc[i][j]);
        }
        __syncthreads();
    }

    float bb[4];
    *(float4*)bb = *(const float4*)&bo[n0 + tx * 4];
#pragma unroll
    for (int i = 0; i < 8; i++) {
        int s = s0 + ty * 8 + i;
        float4 r = make_float4(acc[i][0] + bb[0], acc[i][1] + bb[1],
                               acc[i][2] + bb[2], acc[i][3] + bb[3]);
        *(float4*)&out[(size_t)s * DMODEL + n0 + tx * 4] = r;
    }
}

// ---------------------------------------------------------------------------
extern "C" void kernel_launch(void* const* d_in, const int* in_sizes, int n_in,
                              void* d_out, int out_size)
{
    const float* x  = (const float*)d_in[0];
    const float* Wq = (const float*)d_in[1];
    const float* Wk = (const float*)d_in[2];
    const float* Wv = (const float*)d_in[3];
    const float* bq = (const float*)d_in[4];
    const float* bk = (const float*)d_in[5];
    const float* bv = (const float*)d_in[6];
    const float* Wo = (const float*)d_in[7];
    const float* bo = (const float*)d_in[8];
    float* out = (float*)d_out;

    cudaFuncSetAttribute(attn_kernel, cudaFuncAttributeMaxDynamicSharedMemorySize,
                         (int)ATTN_SMEM_BYTES);

    qkv_kernel<<<dim3(S_LEN / 128, 3 * NHEAD), 256>>>(x, Wq, Wk, Wv, bq, bk, bv);
    attn_kernel<<<dim3(S_LEN / QTILE, NHEAD), 256, ATTN_SMEM_BYTES>>>();
    proj_kernel<<<dim3(S_LEN / 128, DMODEL / 64), 256>>>(Wo, bo, out);
}

// round 3
// speedup vs baseline: 2.3416x; 1.2931x over previous
#include <cuda_runtime.h>
#include <cuda_bf16.h>
#include <cstddef>
#include <cstdint>

#define S_LEN 4096
#define DMODEL 768
#define NHEAD 12
#define HDIM 64
#define QTILE 128
#define KTILE 64

// scratch: Q/K/V [3][H][S][HD] and concat [S][D]
__device__ float g_qkv[3 * NHEAD * S_LEN * HDIM];
__device__ float g_concat[(size_t)S_LEN * DMODEL];

__device__ __forceinline__ uint32_t f2tf(float f) {
    uint32_t r;
    asm("cvt.rna.tf32.f32 %0, %1;" : "=r"(r) : "f"(f));
    return r;
}

__device__ __forceinline__ void mma_tf32(float c[4],
                                         uint32_t a0, uint32_t a1, uint32_t a2, uint32_t a3,
                                         uint32_t b0, uint32_t b1) {
    asm volatile(
        "mma.sync.aligned.m16n8k8.row.col.f32.tf32.tf32.f32 "
        "{%0,%1,%2,%3}, {%4,%5,%6,%7}, {%8,%9}, {%0,%1,%2,%3};"
        : "+f"(c[0]), "+f"(c[1]), "+f"(c[2]), "+f"(c[3])
        : "r"(a0), "r"(a1), "r"(a2), "r"(a3), "r"(b0), "r"(b1));
}

// ---------------------------------------------------------------------------
// Shared tf32 GEMM core: C[128 x 64] = A[128 x 768] * B[768 x 64] + bias
// 8 warps in 4(M) x 2(N) grid; each warp 32x32; K staged in chunks of 32.
// sA: [128][36] (row-major A), sB: [64][36] (B transposed to [n][k]).
// Fragment reads are bank-conflict-free: bank = 4*quad + qt.
// ---------------------------------------------------------------------------
#define GS_A (128 * 36)
#define GS_B (64 * 36)

__device__ __forceinline__ void gemm_128x64_tf32(
    uint32_t* __restrict__ sA, uint32_t* __restrict__ sB,
    const float* __restrict__ Arow, int lda,   // A + s0*lda
    const float* __restrict__ Bmat, int ldb,   // B[k][colbase..]
    const float* __restrict__ bias,            // bias + colbase
    float* __restrict__ Orow, int ldo)         // O + s0*ldo + colbase
{
    const int tid  = threadIdx.x;
    const int wid  = tid >> 5;
    const int lane = tid & 31;
    const int quad = lane >> 2;    // 0..7
    const int qt   = lane & 3;     // 0..3
    const int mw   = wid & 3;      // 4 m-warps
    const int nw   = wid >> 2;     // 2 n-warps

    float acc[2][4][4];
#pragma unroll
    for (int mi = 0; mi < 2; mi++)
#pragma unroll
        for (int ni = 0; ni < 4; ni++)
#pragma unroll
            for (int j = 0; j < 4; j++) acc[mi][ni][j] = 0.f;

    for (int k0 = 0; k0 < DMODEL; k0 += 32) {
        // stage A tile 128x32 (fp32 -> tf32), row-major stride 36
#pragma unroll
        for (int i = tid; i < 1024; i += 256) {
            int row = i >> 3, cg = (i & 7) * 4;
            float4 v = *(const float4*)&Arow[(size_t)row * lda + k0 + cg];
            uint32_t* d = &sA[row * 36 + cg];
            d[0] = f2tf(v.x); d[1] = f2tf(v.y); d[2] = f2tf(v.z); d[3] = f2tf(v.w);
        }
        // stage B tile 32x64 transposed to sB[n][k], stride 36
#pragma unroll
        for (int i = tid; i < 512; i += 256) {
            int kk = i >> 4, e = (i & 15) * 4;
            float4 v = *(const float4*)&Bmat[(size_t)(k0 + kk) * ldb + e];
            sB[(e + 0) * 36 + kk] = f2tf(v.x);
            sB[(e + 1) * 36 + kk] = f2tf(v.y);
            sB[(e + 2) * 36 + kk] = f2tf(v.z);
            sB[(e + 3) * 36 + kk] = f2tf(v.w);
        }
        __syncthreads();

#pragma unroll
        for (int ks = 0; ks < 4; ks++) {
            uint32_t a[2][4];
#pragma unroll
            for (int mi = 0; mi < 2; mi++) {
                int base = mw * 32 + mi * 16;
                a[mi][0] = sA[(base + quad    ) * 36 + ks * 8 + qt];
                a[mi][1] = sA[(base + quad + 8) * 36 + ks * 8 + qt];
                a[mi][2] = sA[(base + quad    ) * 36 + ks * 8 + qt + 4];
                a[mi][3] = sA[(base + quad + 8) * 36 + ks * 8 + qt + 4];
            }
            uint32_t b[4][2];
#pragma unroll
            for (int ni = 0; ni < 4; ni++) {
                int cb = nw * 32 + ni * 8;
                b[ni][0] = sB[(cb + quad) * 36 + ks * 8 + qt];
                b[ni][1] = sB[(cb + quad) * 36 + ks * 8 + qt + 4];
            }
#pragma unroll
            for (int mi = 0; mi < 2; mi++)
#pragma unroll
                for (int ni = 0; ni < 4; ni++)
                    mma_tf32(acc[mi][ni], a[mi][0], a[mi][1], a[mi][2], a[mi][3],
                             b[ni][0], b[ni][1]);
        }
        __syncthreads();
    }

    // epilogue: add bias, write fp32
#pragma unroll
    for (int mi = 0; mi < 2; mi++) {
        int r0 = mw * 32 + mi * 16 + quad;
        int r1 = r0 + 8;
#pragma unroll
        for (int ni = 0; ni < 4; ni++) {
            int c = nw * 32 + ni * 8 + 2 * qt;
            float b0 = bias[c], b1 = bias[c + 1];
            float2 w0 = make_float2(acc[mi][ni][0] + b0, acc[mi][ni][1] + b1);
            float2 w1 = make_float2(acc[mi][ni][2] + b0, acc[mi][ni][3] + b1);
            *(float2*)&Orow[(size_t)r0 * ldo + c] = w0;
            *(float2*)&Orow[(size_t)r1 * ldo + c] = w1;
        }
    }
}

// ---------------------------------------------------------------------------
// Kernel 1: fused QKV projection via tf32 mma. grid (32, 36), block 256.
// ---------------------------------------------------------------------------
__global__ void __launch_bounds__(256) qkv_kernel(
    const float* __restrict__ x,
    const float* __restrict__ Wq, const float* __restrict__ Wk, const float* __restrict__ Wv,
    const float* __restrict__ bq, const float* __restrict__ bk, const float* __restrict__ bv)
{
    __shared__ uint32_t sm[GS_A + GS_B];
    const int mat = blockIdx.y / NHEAD;
    const int h   = blockIdx.y % NHEAD;
    const int s0  = blockIdx.x * 128;

    const float* W    = (mat == 0 ? Wq : (mat == 1 ? Wk : Wv)) + (size_t)h * DMODEL * HDIM;
    const float* bias = (mat == 0 ? bq : (mat == 1 ? bk : bv)) + h * HDIM;
    float* O = g_qkv + ((size_t)(mat * NHEAD + h)) * S_LEN * HDIM + (size_t)s0 * HDIM;

    gemm_128x64_tf32(sm, sm + GS_A, x + (size_t)s0 * DMODEL, DMODEL,
                     W, HDIM, bias, O, HDIM);
}

// ---------------------------------------------------------------------------
// Kernel 2: flash attention with tf32 mma.sync (unchanged from R2).
// ---------------------------------------------------------------------------
#define SK_STRIDE 68
#define SV_STRIDE 72
#define SP_STRIDE 68
#define ATTN_SMEM_WORDS (KTILE * SK_STRIDE + KTILE * SV_STRIDE + QTILE * SP_STRIDE)
#define ATTN_SMEM_BYTES ((size_t)ATTN_SMEM_WORDS * 4)

__global__ void __launch_bounds__(256) attn_kernel()
{
    extern __shared__ uint32_t sm[];
    uint32_t* sK = sm;
    uint32_t* sV = sK + KTILE * SK_STRIDE;
    uint32_t* sP = sV + KTILE * SV_STRIDE;

    const int h  = blockIdx.y;
    const int q0 = blockIdx.x * QTILE;
    const float* Q = g_qkv + ((size_t)(0 * NHEAD + h)) * S_LEN * HDIM;
    const float* K = g_qkv + ((size_t)(1 * NHEAD + h)) * S_LEN * HDIM;
    const float* V = g_qkv + ((size_t)(2 * NHEAD + h)) * S_LEN * HDIM;

    const int tid  = threadIdx.x;
    const int wid  = tid >> 5;
    const int lane = tid & 31;
    const int quad = lane >> 2;
    const int qt   = lane & 3;
    const int mrow = q0 + wid * 16;

    uint32_t qa[8][4];
#pragma unroll
    for (int ks = 0; ks < 8; ks++) {
        int c = ks * 8 + qt;
        qa[ks][0] = f2tf(Q[(size_t)(mrow + quad    ) * HDIM + c    ] * 0.125f);
        qa[ks][1] = f2tf(Q[(size_t)(mrow + quad + 8) * HDIM + c    ] * 0.125f);
        qa[ks][2] = f2tf(Q[(size_t)(mrow + quad    ) * HDIM + c + 4] * 0.125f);
        qa[ks][3] = f2tf(Q[(size_t)(mrow + quad + 8) * HDIM + c + 4] * 0.125f);
    }

    float o[8][4];
#pragma unroll
    for (int n = 0; n < 8; n++)
#pragma unroll
        for (int j = 0; j < 4; j++) o[n][j] = 0.f;
    float m0 = -1e30f, m1 = -1e30f, l0 = 0.f, l1 = 0.f;

    uint32_t* pbase = sP + (wid * 16) * SP_STRIDE;

    for (int kt = 0; kt < S_LEN / KTILE; kt++) {
        const int s0 = kt * KTILE;
        __syncthreads();

#pragma unroll
        for (int i = tid; i < KTILE * 16; i += 256) {
            int r = i >> 4, cg = (i & 15) * 4;
            float4 kv = *(const float4*)&K[(size_t)(s0 + r) * HDIM + cg];
            uint32_t* dk = &sK[r * SK_STRIDE + cg];
            dk[0] = f2tf(kv.x); dk[1] = f2tf(kv.y); dk[2] = f2tf(kv.z); dk[3] = f2tf(kv.w);
            float4 vv = *(const float4*)&V[(size_t)(s0 + r) * HDIM + cg];
            uint32_t* dv = &sV[r * SV_STRIDE + cg];
            dv[0] = f2tf(vv.x); dv[1] = f2tf(vv.y); dv[2] = f2tf(vv.z); dv[3] = f2tf(vv.w);
        }
        __syncthreads();

        float sc[8][4];
#pragma unroll
        for (int n = 0; n < 8; n++)
#pragma unroll
            for (int j = 0; j < 4; j++) sc[n][j] = 0.f;

#pragma unroll
        for (int ks = 0; ks < 8; ks++) {
#pragma unroll
            for (int n = 0; n < 8; n++) {
                const uint32_t* kb = &sK[(n * 8 + quad) * SK_STRIDE + ks * 8 + qt];
                mma_tf32(sc[n], qa[ks][0], qa[ks][1], qa[ks][2], qa[ks][3], kb[0], kb[4]);
            }
        }

        float rmax0 = -1e30f, rmax1 = -1e30f;
#pragma unroll
        for (int n = 0; n < 8; n++) {
            rmax0 = fmaxf(rmax0, fmaxf(sc[n][0], sc[n][1]));
            rmax1 = fmaxf(rmax1, fmaxf(sc[n][2], sc[n][3]));
        }
        rmax0 = fmaxf(rmax0, __shfl_xor_sync(0xffffffffu, rmax0, 1));
        rmax0 = fmaxf(rmax0, __shfl_xor_sync(0xffffffffu, rmax0, 2));
        rmax1 = fmaxf(rmax1, __shfl_xor_sync(0xffffffffu, rmax1, 1));
        rmax1 = fmaxf(rmax1, __shfl_xor_sync(0xffffffffu, rmax1, 2));

        float nm0 = fmaxf(m0, rmax0), nm1 = fmaxf(m1, rmax1);
        float al0 = __expf(m0 - nm0), al1 = __expf(m1 - nm1);
        m0 = nm0; m1 = nm1;

        float rs0 = 0.f, rs1 = 0.f;
#pragma unroll
        for (int n = 0; n < 8; n++) {
            sc[n][0] = __expf(sc[n][0] - nm0); rs0 += sc[n][0];
            sc[n][1] = __expf(sc[n][1] - nm0); rs0 += sc[n][1];
            sc[n][2] = __expf(sc[n][2] - nm1); rs1 += sc[n][2];
            sc[n][3] = __expf(sc[n][3] - nm1); rs1 += sc[n][3];
        }
        rs0 += __shfl_xor_sync(0xffffffffu, rs0, 1);
        rs0 += __shfl_xor_sync(0xffffffffu, rs0, 2);
        rs1 += __shfl_xor_sync(0xffffffffu, rs1, 1);
        rs1 += __shfl_xor_sync(0xffffffffu, rs1, 2);
        l0 = l0 * al0 + rs0;
        l1 = l1 * al1 + rs1;

#pragma unroll
        for (int n = 0; n < 8; n++) {
            o[n][0] *= al0; o[n][1] *= al0;
            o[n][2] *= al1; o[n][3] *= al1;
        }

#pragma unroll
        for (int n = 0; n < 8; n++) {
            int c = n * 8 + 2 * qt;
            pbase[(quad    ) * SP_STRIDE + c    ] = f2tf(sc[n][0]);
            pbase[(quad    ) * SP_STRIDE + c + 1] = f2tf(sc[n][1]);
            pbase[(quad + 8) * SP_STRIDE + c    ] = f2tf(sc[n][2]);
            pbase[(quad + 8) * SP_STRIDE + c + 1] = f2tf(sc[n][3]);
        }
        __syncwarp();

#pragma unroll
        for (int ks = 0; ks < 8; ks++) {
            uint32_t pa0 = pbase[(quad    ) * SP_STRIDE + ks * 8 + qt];
            uint32_t pa1 = pbase[(quad + 8) * SP_STRIDE + ks * 8 + qt];
            uint32_t pa2 = pbase[(quad    ) * SP_STRIDE + ks * 8 + qt + 4];
            uint32_t pa3 = pbase[(quad + 8) * SP_STRIDE + ks * 8 + qt + 4];
#pragma unroll
            for (int n = 0; n < 8; n++) {
                const uint32_t* vb = &sV[(ks * 8 + qt) * SV_STRIDE + n * 8 + quad];
                mma_tf32(o[n], pa0, pa1, pa2, pa3, vb[0], vb[4 * SV_STRIDE]);
            }
        }
    }

    float il0 = 1.f / l0, il1 = 1.f / l1;
    const int r0g = mrow + quad, r1g = mrow + quad + 8;
#pragma unroll
    for (int n = 0; n < 8; n++) {
        int col = h * HDIM + n * 8 + 2 * qt;
        float2 w0 = make_float2(o[n][0] * il0, o[n][1] * il0);
        float2 w1 = make_float2(o[n][2] * il1, o[n][3] * il1);
        *(float2*)&g_concat[(size_t)r0g * DMODEL + col] = w0;
        *(float2*)&g_concat[(size_t)r1g * DMODEL + col] = w1;
    }
}

// ---------------------------------------------------------------------------
// Kernel 3: output projection via tf32 mma. grid (32, 12), block 256.
// ---------------------------------------------------------------------------
__global__ void __launch_bounds__(256) proj_kernel(
    const float* __restrict__ Wo, const float* __restrict__ bo, float* __restrict__ out)
{
    __shared__ uint32_t sm[GS_A + GS_B];
    const int s0 = blockIdx.x * 128;
    const int n0 = blockIdx.y * 64;

    gemm_128x64_tf32(sm, sm + GS_A,
                     g_concat + (size_t)s0 * DMODEL, DMODEL,
                     Wo + n0, DMODEL, bo + n0,
                     out + (size_t)s0 * DMODEL + n0, DMODEL);
}

// ---------------------------------------------------------------------------
extern "C" void kernel_launch(void* const* d_in, const int* in_sizes, int n_in,
                              void* d_out, int out_size)
{
    const float* x  = (const float*)d_in[0];
    const float* Wq = (const float*)d_in[1];
    const float* Wk = (const float*)d_in[2];
    const float* Wv = (const float*)d_in[3];
    const float* bq = (const float*)d_in[4];
    const float* bk = (const float*)d_in[5];
    const float* bv = (const float*)d_in[6];
    const float* Wo = (const float*)d_in[7];
    const float* bo = (const float*)d_in[8];
    float* out = (float*)d_out;

    cudaFuncSetAttribute(attn_kernel, cudaFuncAttributeMaxDynamicSharedMemorySize,
                         (int)ATTN_SMEM_BYTES);

    qkv_kernel<<<dim3(S_LEN / 128, 3 * NHEAD), 256>>>(x, Wq, Wk, Wv, bq, bk, bv);
    attn_kernel<<<dim3(S_LEN / QTILE, NHEAD), 256, ATTN_SMEM_BYTES>>>();
    proj_kernel<<<dim3(S_LEN / 128, DMODEL / 64), 256>>>(Wo, bo, out);
}